// round 1
// baseline (speedup 1.0000x reference)
#include <cuda_runtime.h>
#include <math.h>

// Problem constants (fixed by the reference).
#define NN 100000
#define EE 1600000
#define NB_MLP 8

// ---------------- scratch (static device globals; no allocations) ----------------
__device__ int      d_deg[NN];
__device__ int      d_rowptr[NN + 1];
__device__ int      d_cursor[NN];
__device__ int      d_scanb[128];
__device__ int      d_boff[128];
__device__ int      d_idx64;            // 1 if edge_index/batch are int64, 0 if int32
__device__ int      d_csrsrc[EE];
__device__ float2   d_csrea[EE];
__device__ float    d_csrw[EE];
__device__ float    d_hpre[(size_t)NN * 128];   // hpre (conv1: [N,64], conv2: [N,128]); APPNP pong
__device__ float    d_h1[(size_t)NN * 128];     // conv1 output
__device__ float    d_x0[(size_t)NN * 128];     // conv2 output = APPNP teleport term
__device__ float    d_pp[(size_t)NN * 128];     // APPNP ping
__device__ float    d_gate[NN];
__device__ float    d_expg[NN];
__device__ unsigned d_bmax[64];
__device__ float    d_bsum[64];

// ---------------- helpers ----------------
__device__ __forceinline__ float gelu_f(float x) {
    return 0.5f * x * (1.0f + erff(x * 0.7071067811865476f));
}
__device__ __forceinline__ unsigned ford(float f) {
    unsigned u = __float_as_uint(f);
    return (u & 0x80000000u) ? ~u : (u | 0x80000000u);
}
__device__ __forceinline__ float funord(unsigned u) {
    return (u & 0x80000000u) ? __uint_as_float(u & 0x7fffffffu) : __uint_as_float(~u);
}
// Index load that works for both int32 and int64 source buffers.
__device__ __forceinline__ int ld_idx(const void* p, long long i) {
    if (d_idx64) return (int)__ldg(&((const long long*)p)[i]);
    return __ldg(&((const int*)p)[i]);
}

// ---------------- dtype detection ----------------
__global__ void k_detect(const void* ei, long long total_elems) {
    if (threadIdx.x == 0 && blockIdx.x == 0) {
        const int* w = (const int*)ei;
        int ok = 1;
        long long stride = (total_elems - 2) / 64;
        for (int t = 0; t < 64; t++) {
            long long j = 1 + (long long)t * stride;
            int lo = w[2 * j];
            int hi = w[2 * j + 1];
            if (hi != 0 || lo < 0) { ok = 0; break; }
        }
        d_idx64 = ok;
    }
}

// ---------------- CSR construction ----------------
__global__ void k_zero_deg(int n) {
    int i = blockIdx.x * blockDim.x + threadIdx.x;
    if (i < n) d_deg[i] = 0;
}
__global__ void k_count(const void* ei, int eN) {
    int i = blockIdx.x * blockDim.x + threadIdx.x;
    if (i >= eN) return;
    int dst = ld_idx(ei, (long long)eN + i);
    atomicAdd(&d_deg[dst], 1);
}
__global__ void k_scan1(int n) {
    __shared__ int sh[1024];
    int tid = threadIdx.x;
    int i = blockIdx.x * 1024 + tid;
    int v = (i < n) ? d_deg[i] : 0;
    sh[tid] = v;
    __syncthreads();
    for (int off = 1; off < 1024; off <<= 1) {
        int t = (tid >= off) ? sh[tid - off] : 0;
        __syncthreads();
        sh[tid] += t;
        __syncthreads();
    }
    if (i < n) d_rowptr[i] = sh[tid] - v;       // block-local exclusive
    if (tid == 1023) d_scanb[blockIdx.x] = sh[1023];
}
__global__ void k_scan2(int nb) {
    __shared__ int sh[128];
    int tid = threadIdx.x;
    int v = (tid < nb) ? d_scanb[tid] : 0;
    sh[tid] = v;
    __syncthreads();
    for (int off = 1; off < 128; off <<= 1) {
        int t = (tid >= off) ? sh[tid - off] : 0;
        __syncthreads();
        sh[tid] += t;
        __syncthreads();
    }
    d_boff[tid] = sh[tid] - v;                  // exclusive block offsets
}
__global__ void k_scan3(int n, int eN) {
    int i = blockIdx.x * blockDim.x + threadIdx.x;
    if (i < n) {
        int r = d_rowptr[i] + d_boff[i >> 10];
        d_rowptr[i] = r;
        d_cursor[i] = r;
    }
    if (i == 0) d_rowptr[n] = eN;
}
__global__ void k_build(const void* ei, const float* __restrict__ ea, int eN) {
    int i = blockIdx.x * blockDim.x + threadIdx.x;
    if (i >= eN) return;
    int s = ld_idx(ei, i);
    int d = ld_idx(ei, (long long)eN + i);
    int pos = atomicAdd(&d_cursor[d], 1);
    d_csrsrc[pos] = s;
    d_csrea[pos] = ((const float2*)ea)[i];
    // APPNP gcn_norm weight: rsqrt(1+indeg[src]) * rsqrt(1+indeg[dst])
    d_csrw[pos] = rsqrtf((float)(d_deg[s] + 1)) * rsqrtf((float)(d_deg[d] + 1));
}

// ---------------- GINE aggregation (pull via CSR) ----------------
// D=64: warp per node, float2 per lane. out -> d_hpre ([N,64])
__global__ void k_agg64(const float* __restrict__ x, const float* __restrict__ We,
                        const float* __restrict__ be, int n) {
    int wid = (blockIdx.x * blockDim.x + threadIdx.x) >> 5;
    if (wid >= n) return;
    int lane = threadIdx.x & 31;
    int f = lane * 2;
    float w0a = __ldg(&We[f]),      w0b = __ldg(&We[f + 1]);
    float w1a = __ldg(&We[64 + f]), w1b = __ldg(&We[64 + f + 1]);
    float ba = __ldg(&be[f]),       bb = __ldg(&be[f + 1]);
    int beg = d_rowptr[wid], end = d_rowptr[wid + 1];
    float a0 = 0.f, a1 = 0.f;
    for (int e = beg; e < end; e++) {
        int s = d_csrsrc[e];
        float2 eav = d_csrea[e];
        float2 xv = *(const float2*)&x[(size_t)s * 64 + f];
        a0 += fmaxf(xv.x + eav.x * w0a + eav.y * w1a + ba, 0.f);
        a1 += fmaxf(xv.y + eav.x * w0b + eav.y * w1b + bb, 0.f);
    }
    float2 xs = *(const float2*)&x[(size_t)wid * 64 + f];
    float2 r;
    r.x = xs.x + a0;
    r.y = xs.y + a1;
    *(float2*)&d_hpre[(size_t)wid * 64 + f] = r;
}

// D=128: warp per node, float4 per lane, edge-unroll 2. in=d_h1 -> out=d_hpre ([N,128])
__global__ void k_agg128(const float* __restrict__ We, const float* __restrict__ be, int n) {
    int wid = (blockIdx.x * blockDim.x + threadIdx.x) >> 5;
    if (wid >= n) return;
    int lane = threadIdx.x & 31;
    int f = lane * 4;
    const float* __restrict__ xin = d_h1;
    float4 w0 = *(const float4*)&We[f];
    float4 w1 = *(const float4*)&We[128 + f];
    float4 bb = *(const float4*)&be[f];
    int beg = d_rowptr[wid], end = d_rowptr[wid + 1];
    float ax = 0.f, ay = 0.f, az = 0.f, aw = 0.f;
    int e = beg;
    for (; e + 2 <= end; e += 2) {
        int s0 = d_csrsrc[e], s1 = d_csrsrc[e + 1];
        float2 e0 = d_csrea[e], e1 = d_csrea[e + 1];
        float4 v0 = *(const float4*)&xin[(size_t)s0 * 128 + f];
        float4 v1 = *(const float4*)&xin[(size_t)s1 * 128 + f];
        ax += fmaxf(v0.x + e0.x * w0.x + e0.y * w1.x + bb.x, 0.f)
            + fmaxf(v1.x + e1.x * w0.x + e1.y * w1.x + bb.x, 0.f);
        ay += fmaxf(v0.y + e0.x * w0.y + e0.y * w1.y + bb.y, 0.f)
            + fmaxf(v1.y + e1.x * w0.y + e1.y * w1.y + bb.y, 0.f);
        az += fmaxf(v0.z + e0.x * w0.z + e0.y * w1.z + bb.z, 0.f)
            + fmaxf(v1.z + e1.x * w0.z + e1.y * w1.z + bb.z, 0.f);
        aw += fmaxf(v0.w + e0.x * w0.w + e0.y * w1.w + bb.w, 0.f)
            + fmaxf(v1.w + e1.x * w0.w + e1.y * w1.w + bb.w, 0.f);
    }
    for (; e < end; e++) {
        int s = d_csrsrc[e];
        float2 e0 = d_csrea[e];
        float4 v0 = *(const float4*)&xin[(size_t)s * 128 + f];
        ax += fmaxf(v0.x + e0.x * w0.x + e0.y * w1.x + bb.x, 0.f);
        ay += fmaxf(v0.y + e0.x * w0.y + e0.y * w1.y + bb.y, 0.f);
        az += fmaxf(v0.z + e0.x * w0.z + e0.y * w1.z + bb.z, 0.f);
        aw += fmaxf(v0.w + e0.x * w0.w + e0.y * w1.w + bb.w, 0.f);
    }
    float4 xs = *(const float4*)&xin[(size_t)wid * 128 + f];
    float4 r;
    r.x = xs.x + ax; r.y = xs.y + ay; r.z = xs.z + az; r.w = xs.w + aw;
    *(float4*)&d_hpre[(size_t)wid * 128 + f] = r;
}

// ---------------- MLP + LayerNorm (fused, register tile of 8 nodes) ----------------
// GL=true : conv1 : out = LN(gelu(gelu(in@W1+b1)@W2+b2)), in=d_hpre[N,64],  out=d_h1
// GL=false: conv2 : out = LN(     gelu(in@W1+b1)@W2+b2 ), in=d_hpre[N,128], out=d_x0
template <int DIN, bool GL>
__global__ void k_mlp(const float* __restrict__ W1, const float* __restrict__ b1,
                      const float* __restrict__ W2, const float* __restrict__ b2,
                      const float* __restrict__ gm, const float* __restrict__ bt, int n) {
    __shared__ __align__(16) float in_sh[NB_MLP][DIN];
    __shared__ __align__(16) float t_sh[NB_MLP][128];
    __shared__ float u_sh[NB_MLP][128];
    __shared__ float st[NB_MLP][2];
    const float* __restrict__ in = d_hpre;
    float* __restrict__ out = GL ? d_h1 : d_x0;

    int tid = threadIdx.x;
    int base = blockIdx.x * NB_MLP;
    for (int idx = tid; idx < NB_MLP * DIN; idx += 128) {
        int nn = idx / DIN, k = idx % DIN;
        int node = base + nn;
        in_sh[nn][k] = (node < n) ? __ldg(&in[(size_t)node * DIN + k]) : 0.f;
    }
    __syncthreads();
    int f = tid;
    float acc[NB_MLP];
    {
        float bv = __ldg(&b1[f]);
#pragma unroll
        for (int i = 0; i < NB_MLP; i++) acc[i] = bv;
    }
    for (int k = 0; k < DIN; k += 4) {
        float wa = __ldg(&W1[(k + 0) * 128 + f]);
        float wb = __ldg(&W1[(k + 1) * 128 + f]);
        float wc = __ldg(&W1[(k + 2) * 128 + f]);
        float wd = __ldg(&W1[(k + 3) * 128 + f]);
#pragma unroll
        for (int i = 0; i < NB_MLP; i++) {
            float4 iv = *(const float4*)&in_sh[i][k];
            acc[i] += iv.x * wa + iv.y * wb + iv.z * wc + iv.w * wd;
        }
    }
#pragma unroll
    for (int i = 0; i < NB_MLP; i++) t_sh[i][f] = gelu_f(acc[i]);
    __syncthreads();
    {
        float bv = __ldg(&b2[f]);
#pragma unroll
        for (int i = 0; i < NB_MLP; i++) acc[i] = bv;
    }
    for (int k = 0; k < 128; k += 4) {
        float wa = __ldg(&W2[(k + 0) * 128 + f]);
        float wb = __ldg(&W2[(k + 1) * 128 + f]);
        float wc = __ldg(&W2[(k + 2) * 128 + f]);
        float wd = __ldg(&W2[(k + 3) * 128 + f]);
#pragma unroll
        for (int i = 0; i < NB_MLP; i++) {
            float4 tv = *(const float4*)&t_sh[i][k];
            acc[i] += tv.x * wa + tv.y * wb + tv.z * wc + tv.w * wd;
        }
    }
#pragma unroll
    for (int i = 0; i < NB_MLP; i++) {
        float u = acc[i];
        if (GL) u = gelu_f(u);     // conv1 applies gelu BEFORE layernorm
        u_sh[i][f] = u;
    }
    __syncthreads();
    {
        int g = tid >> 4, l = tid & 15;   // group g (16 lanes) reduces node g
        float s = 0.f, q = 0.f;
#pragma unroll
        for (int m = 0; m < 8; m++) {
            float v = u_sh[g][l + 16 * m];
            s += v;
            q += v * v;
        }
#pragma unroll
        for (int off = 8; off > 0; off >>= 1) {
            s += __shfl_xor_sync(0xffffffffu, s, off);
            q += __shfl_xor_sync(0xffffffffu, q, off);
        }
        if (l == 0) {
            float mu = s * (1.f / 128.f);
            float var = q * (1.f / 128.f) - mu * mu;
            st[g][0] = mu;
            st[g][1] = rsqrtf(var + 1e-5f);
        }
    }
    __syncthreads();
    float gv = __ldg(&gm[f]), bv2 = __ldg(&bt[f]);
#pragma unroll
    for (int i = 0; i < NB_MLP; i++) {
        int node = base + i;
        if (node < n)
            out[(size_t)node * 128 + f] = (u_sh[i][f] - st[i][0]) * st[i][1] * gv + bv2;
    }
}

// ---------------- APPNP step (pull, warp per node, float4 per lane, edge-unroll 4) ----------------
// insel: 0=d_x0 1=d_pp 2=d_hpre ; outsel: 1=d_pp 2=d_hpre 3=extout
__global__ void k_appnp(int insel, int outsel, float* __restrict__ extout, int n) {
    const float* __restrict__ hin = (insel == 0) ? d_x0 : ((insel == 1) ? d_pp : d_hpre);
    float* __restrict__ hout = (outsel == 1) ? d_pp : ((outsel == 2) ? d_hpre : extout);
    int wid = (blockIdx.x * blockDim.x + threadIdx.x) >> 5;
    if (wid >= n) return;
    int lane = threadIdx.x & 31;
    int f = lane * 4;
    int beg = d_rowptr[wid], end = d_rowptr[wid + 1];
    float ax = 0.f, ay = 0.f, az = 0.f, aw = 0.f;
    int e = beg;
    for (; e + 4 <= end; e += 4) {
        int s0 = d_csrsrc[e],     s1 = d_csrsrc[e + 1];
        int s2 = d_csrsrc[e + 2], s3 = d_csrsrc[e + 3];
        float w0 = d_csrw[e],     w1 = d_csrw[e + 1];
        float w2 = d_csrw[e + 2], w3 = d_csrw[e + 3];
        float4 v0 = *(const float4*)&hin[(size_t)s0 * 128 + f];
        float4 v1 = *(const float4*)&hin[(size_t)s1 * 128 + f];
        float4 v2 = *(const float4*)&hin[(size_t)s2 * 128 + f];
        float4 v3 = *(const float4*)&hin[(size_t)s3 * 128 + f];
        ax += w0 * v0.x + w1 * v1.x + w2 * v2.x + w3 * v3.x;
        ay += w0 * v0.y + w1 * v1.y + w2 * v2.y + w3 * v3.y;
        az += w0 * v0.z + w1 * v1.z + w2 * v2.z + w3 * v3.z;
        aw += w0 * v0.w + w1 * v1.w + w2 * v2.w + w3 * v3.w;
    }
    for (; e < end; e++) {
        int s = d_csrsrc[e];
        float w = d_csrw[e];
        float4 v = *(const float4*)&hin[(size_t)s * 128 + f];
        ax += w * v.x; ay += w * v.y; az += w * v.z; aw += w * v.w;
    }
    float sw = 1.f / ((float)d_deg[wid] + 1.f);
    float4 hv = *(const float4*)&hin[(size_t)wid * 128 + f];
    float4 xv = *(const float4*)&d_x0[(size_t)wid * 128 + f];
    float4 r;
    r.x = 0.9f * (ax + sw * hv.x) + 0.1f * xv.x;
    r.y = 0.9f * (ay + sw * hv.y) + 0.1f * xv.y;
    r.z = 0.9f * (az + sw * hv.z) + 0.1f * xv.z;
    r.w = 0.9f * (aw + sw * hv.w) + 0.1f * xv.w;
    *(float4*)&hout[(size_t)wid * 128 + f] = r;
}

// ---------------- gate + attentional pooling ----------------
__global__ void k_poolinit(float* __restrict__ outg) {
    int i = blockIdx.x * blockDim.x + threadIdx.x;
    if (i < 64) {
        d_bmax[i] = 0x007FFFFFu;   // ford(-inf)
        d_bsum[i] = 0.f;
    }
    if (i < 64 * 128) outg[i] = 0.f;
}
__global__ void k_gate(const float* __restrict__ h, const float* __restrict__ Wg1,
                       const float* __restrict__ bg1, const float* __restrict__ Wg2,
                       const float* __restrict__ bg2, const void* batch, int n) {
    __shared__ __align__(16) float hsh[4][128];
    __shared__ float wsum[8];
    int sub = threadIdx.x >> 6;        // 4 nodes / block, 64 threads each
    int j = threadIdx.x & 63;
    int node = blockIdx.x * 4 + sub;
    if (node < n) {
        hsh[sub][j]      = __ldg(&h[(size_t)node * 128 + j]);
        hsh[sub][j + 64] = __ldg(&h[(size_t)node * 128 + j + 64]);
    }
    __syncthreads();
    float c = 0.f;
    if (node < n) {
        float a = __ldg(&bg1[j]);
        for (int k = 0; k < 128; k += 4) {
            float4 hv = *(const float4*)&hsh[sub][k];
            a += hv.x * __ldg(&Wg1[(k + 0) * 64 + j]);
            a += hv.y * __ldg(&Wg1[(k + 1) * 64 + j]);
            a += hv.z * __ldg(&Wg1[(k + 2) * 64 + j]);
            a += hv.w * __ldg(&Wg1[(k + 3) * 64 + j]);
        }
        c = gelu_f(a) * __ldg(&Wg2[j]);
    }
#pragma unroll
    for (int off = 16; off > 0; off >>= 1) c += __shfl_xor_sync(0xffffffffu, c, off);
    if ((threadIdx.x & 31) == 0) wsum[threadIdx.x >> 5] = c;
    __syncthreads();
    if (node < n && j == 0) {
        float gvl = wsum[2 * sub] + wsum[2 * sub + 1] + __ldg(&bg2[0]);
        d_gate[node] = gvl;
        int b = ld_idx(batch, node);
        atomicMax(&d_bmax[b], ford(gvl));
    }
}
__global__ void k_exp(const void* batch, int n) {
    int i = blockIdx.x * blockDim.x + threadIdx.x;
    if (i >= n) return;
    int b = ld_idx(batch, i);
    float ev = expf(d_gate[i] - funord(d_bmax[b]));
    d_expg[i] = ev;
    atomicAdd(&d_bsum[b], ev);
}
__global__ void k_pool(const float* __restrict__ h, const void* batch,
                       float* __restrict__ outg, int n) {
    int base = blockIdx.x * 64;           // 64 sorted nodes per block, pre-aggregate per batch
    int f = threadIdx.x;                  // 128 threads = feature
    float acc = 0.f;
    int cb = -1;
    int lim = n - base;
    if (lim > 64) lim = 64;
    for (int j = 0; j < lim; j++) {
        int i = base + j;
        int b = ld_idx(batch, i);
        if (b != cb) {
            if (cb >= 0) atomicAdd(&outg[cb * 128 + f], acc);
            acc = 0.f;
            cb = b;
        }
        float a = d_expg[i] / d_bsum[b];
        acc += a * __ldg(&h[(size_t)i * 128 + f]);
    }
    if (cb >= 0) atomicAdd(&outg[cb * 128 + f], acc);
}

// ---------------- launch ----------------
extern "C" void kernel_launch(void* const* d_in, const int* in_sizes, int n_in,
                              void* d_out, int out_size) {
    const float* x   = (const float*)d_in[0];
    const void*  ei  = d_in[1];
    const void*  bat = d_in[2];
    const float* ea  = (const float*)d_in[3];
    const float* We1 = (const float*)d_in[4];
    const float* be1 = (const float*)d_in[5];
    const float* W1a = (const float*)d_in[6];
    const float* b1a = (const float*)d_in[7];
    const float* W1b = (const float*)d_in[8];
    const float* b1b = (const float*)d_in[9];
    const float* g1  = (const float*)d_in[10];
    const float* bn1 = (const float*)d_in[11];
    const float* We2 = (const float*)d_in[12];
    const float* be2 = (const float*)d_in[13];
    const float* W2a = (const float*)d_in[14];
    const float* b2a = (const float*)d_in[15];
    const float* W2b = (const float*)d_in[16];
    const float* b2b = (const float*)d_in[17];
    const float* g2  = (const float*)d_in[18];
    const float* bn2 = (const float*)d_in[19];
    const float* Wg1 = (const float*)d_in[20];
    const float* bg1 = (const float*)d_in[21];
    const float* Wg2 = (const float*)d_in[22];
    const float* bg2 = (const float*)d_in[23];

    int n = in_sizes[0] / 64;    // 100000
    int e = in_sizes[3] / 2;     // 1600000
    float* out = (float*)d_out;
    float* outh = out;                        // h: [N,128]
    float* outg = out + (size_t)n * 128;      // g: [B,128]

    // CSR preprocessing
    k_detect<<<1, 32>>>(ei, (long long)2 * e);
    k_zero_deg<<<(n + 255) / 256, 256>>>(n);
    k_count<<<(e + 255) / 256, 256>>>(ei, e);
    int sb = (n + 1023) / 1024;
    k_scan1<<<sb, 1024>>>(n);
    k_scan2<<<1, 128>>>(sb);
    k_scan3<<<(n + 255) / 256, 256>>>(n, e);
    k_build<<<(e + 255) / 256, 256>>>(ei, ea, e);

    int wb = (n + 7) / 8;                     // warp-per-node kernels: 8 warps / 256-thread block
    int mb = (n + NB_MLP - 1) / NB_MLP;

    // conv1 + conv2
    k_agg64<<<wb, 256>>>(x, We1, be1, n);
    k_mlp<64, true><<<mb, 128>>>(W1a, b1a, W1b, b1b, g1, bn1, n);
    k_agg128<<<wb, 256>>>(We2, be2, n);
    k_mlp<128, false><<<mb, 128>>>(W2a, b2a, W2b, b2b, g2, bn2, n);

    // APPNP: 16 steps, ping-pong; final step writes straight into d_out's h region
    for (int s = 0; s < 16; s++) {
        int insel  = (s == 0) ? 0 : ((s & 1) ? 1 : 2);
        int outsel = (s == 15) ? 3 : ((s & 1) ? 2 : 1);
        k_appnp<<<wb, 256>>>(insel, outsel, outh, n);
    }

    // gate + per-graph softmax pooling
    k_poolinit<<<32, 256>>>(outg);
    k_gate<<<(n + 3) / 4, 256>>>(outh, Wg1, bg1, Wg2, bg2, bat, n);
    k_exp<<<(n + 255) / 256, 256>>>(bat, n);
    k_pool<<<(n + 63) / 64, 128>>>(outh, bat, outg, n);
}

// round 11
// speedup vs baseline: 1.1306x; 1.1306x over previous
#include <cuda_runtime.h>
#include <cuda_fp16.h>
#include <math.h>

// Problem constants (fixed by the reference).
#define NN 100000
#define EE 1600000
#define NB_MLP 16

// ---------------- scratch (static device globals; no allocations) ----------------
__device__ int      d_deg[NN];
__device__ int      d_rowptr[NN + 1];
__device__ int      d_cursor[NN];
__device__ int      d_scanb[128];
__device__ int      d_boff[128];
__device__ int      d_idx64;            // 1 if edge_index/batch are int64, 0 if int32
__device__ int      d_csrsrc[EE];       // src index (conv kernels)
__device__ int2     d_csredge[EE];      // packed {src, fp32 weight bits} (APPNP kernels)
__device__ float2   d_csrea[EE];
__device__ float    d_hpre[(size_t)NN * 128];   // MLP input (conv1: [N,64], conv2: [N,128])
__device__ float    d_h1[(size_t)NN * 128];     // conv1 output fp32 (self-term in agg128)
__device__ __half   d_xh[(size_t)NN * 64];      // fp16 copy of x (agg64 gather)
__device__ __half   d_h1h[(size_t)NN * 128];    // fp16 copy of conv1 out (agg128 gather)
__device__ __half   d_x0h[(size_t)NN * 128];    // fp16 conv2 out = APPNP x0 / initial state
__device__ __half   d_pa[(size_t)NN * 128];     // APPNP ping (fp16)
__device__ __half   d_pb[(size_t)NN * 128];     // APPNP pong (fp16)
__device__ float    d_gate[NN];
__device__ float    d_expg[NN];
__device__ unsigned d_bmax[64];
__device__ float    d_bsum[64];

// ---------------- helpers ----------------
__device__ __forceinline__ float gelu_f(float x) {
    return 0.5f * x * (1.0f + erff(x * 0.7071067811865476f));
}
__device__ __forceinline__ unsigned ford(float f) {
    unsigned u = __float_as_uint(f);
    return (u & 0x80000000u) ? ~u : (u | 0x80000000u);
}
__device__ __forceinline__ float funord(unsigned u) {
    return (u & 0x80000000u) ? __uint_as_float(u & 0x7fffffffu) : __uint_as_float(~u);
}
// Index load that works for both int32 and int64 source buffers.
__device__ __forceinline__ int ld_idx(const void* p, long long i) {
    if (d_idx64) return (int)__ldg(&((const long long*)p)[i]);
    return __ldg(&((const int*)p)[i]);
}
// Load 4 consecutive halves (8B) and widen to 4 floats.
__device__ __forceinline__ float4 ld_h4(const __half* p) {
    uint2 u = *(const uint2*)p;
    __half2 a = *reinterpret_cast<__half2*>(&u.x);
    __half2 b = *reinterpret_cast<__half2*>(&u.y);
    float2 fa = __half22float2(a);
    float2 fb = __half22float2(b);
    float4 r; r.x = fa.x; r.y = fa.y; r.z = fb.x; r.w = fb.y;
    return r;
}
__device__ __forceinline__ void st_h4(__half* p, float a, float b, float c, float d) {
    uint2 u;
    __half2 lo = __floats2half2_rn(a, b);
    __half2 hi = __floats2half2_rn(c, d);
    u.x = *reinterpret_cast<unsigned*>(&lo);
    u.y = *reinterpret_cast<unsigned*>(&hi);
    *(uint2*)p = u;
}

// ---------------- dtype detection ----------------
__global__ void k_detect(const void* ei, long long total_elems) {
    if (threadIdx.x == 0 && blockIdx.x == 0) {
        const int* w = (const int*)ei;
        int ok = 1;
        long long stride = (total_elems - 2) / 64;
        for (int t = 0; t < 64; t++) {
            long long j = 1 + (long long)t * stride;
            int lo = w[2 * j];
            int hi = w[2 * j + 1];
            if (hi != 0 || lo < 0) { ok = 0; break; }
        }
        d_idx64 = ok;
    }
}

// ---------------- CSR construction ----------------
// merged: zero degree counters + fp16 copy of x
__global__ void k_prep(const float* __restrict__ x, int n, int m) {
    int i = blockIdx.x * blockDim.x + threadIdx.x;
    if (i < n) d_deg[i] = 0;
    if (i < m) d_xh[i] = __float2half(x[i]);
}
__global__ void k_count(const void* ei, int eN) {
    int i = blockIdx.x * blockDim.x + threadIdx.x;
    if (i >= eN) return;
    int dst = ld_idx(ei, (long long)eN + i);
    atomicAdd(&d_deg[dst], 1);
}
__global__ void k_scan1(int n) {
    __shared__ int sh[1024];
    int tid = threadIdx.x;
    int i = blockIdx.x * 1024 + tid;
    int v = (i < n) ? d_deg[i] : 0;
    sh[tid] = v;
    __syncthreads();
    for (int off = 1; off < 1024; off <<= 1) {
        int t = (tid >= off) ? sh[tid - off] : 0;
        __syncthreads();
        sh[tid] += t;
        __syncthreads();
    }
    if (i < n) d_rowptr[i] = sh[tid] - v;       // block-local exclusive
    if (tid == 1023) d_scanb[blockIdx.x] = sh[1023];
}
__global__ void k_scan2(int nb) {
    __shared__ int sh[128];
    int tid = threadIdx.x;
    int v = (tid < nb) ? d_scanb[tid] : 0;
    sh[tid] = v;
    __syncthreads();
    for (int off = 1; off < 128; off <<= 1) {
        int t = (tid >= off) ? sh[tid - off] : 0;
        __syncthreads();
        sh[tid] += t;
        __syncthreads();
    }
    d_boff[tid] = sh[tid] - v;                  // exclusive block offsets
}
__global__ void k_scan3(int n, int eN) {
    int i = blockIdx.x * blockDim.x + threadIdx.x;
    if (i < n) {
        int r = d_rowptr[i] + d_boff[i >> 10];
        d_rowptr[i] = r;
        d_cursor[i] = r;
    }
    if (i == 0) d_rowptr[n] = eN;
}
__global__ void k_build(const void* ei, const float* __restrict__ ea, int eN) {
    int i = blockIdx.x * blockDim.x + threadIdx.x;
    if (i >= eN) return;
    int s = ld_idx(ei, i);
    int d = ld_idx(ei, (long long)eN + i);
    int pos = atomicAdd(&d_cursor[d], 1);
    d_csrsrc[pos] = s;
    d_csrea[pos] = ((const float2*)ea)[i];
    // APPNP gcn_norm weight: rsqrt(1+indeg[src]) * rsqrt(1+indeg[dst])
    float w = rsqrtf((float)(d_deg[s] + 1)) * rsqrtf((float)(d_deg[d] + 1));
    d_csredge[pos] = make_int2(s, __float_as_int(w));
}

// ---------------- GINE aggregation (pull via CSR) ----------------
// D=64: warp per node, 2 feats/lane. gather fp16 d_xh; self fp32 x. out -> d_hpre [N,64]
__global__ void k_agg64(const float* __restrict__ x, const float* __restrict__ We,
                        const float* __restrict__ be, int n) {
    int wid = (blockIdx.x * blockDim.x + threadIdx.x) >> 5;
    if (wid >= n) return;
    int lane = threadIdx.x & 31;
    int f = lane * 2;
    float w0a = __ldg(&We[f]),      w0b = __ldg(&We[f + 1]);
    float w1a = __ldg(&We[64 + f]), w1b = __ldg(&We[64 + f + 1]);
    float ba = __ldg(&be[f]),       bb = __ldg(&be[f + 1]);
    int beg = d_rowptr[wid], end = d_rowptr[wid + 1];
    float a0 = 0.f, a1 = 0.f;
    int e = beg;
    for (; e + 2 <= end; e += 2) {
        int s0 = d_csrsrc[e], s1 = d_csrsrc[e + 1];
        float2 e0 = d_csrea[e], e1 = d_csrea[e + 1];
        float2 v0 = __half22float2(*(const __half2*)&d_xh[(size_t)s0 * 64 + f]);
        float2 v1 = __half22float2(*(const __half2*)&d_xh[(size_t)s1 * 64 + f]);
        a0 += fmaxf(v0.x + e0.x * w0a + e0.y * w1a + ba, 0.f)
            + fmaxf(v1.x + e1.x * w0a + e1.y * w1a + ba, 0.f);
        a1 += fmaxf(v0.y + e0.x * w0b + e0.y * w1b + bb, 0.f)
            + fmaxf(v1.y + e1.x * w0b + e1.y * w1b + bb, 0.f);
    }
    for (; e < end; e++) {
        int s = d_csrsrc[e];
        float2 eav = d_csrea[e];
        float2 xv = __half22float2(*(const __half2*)&d_xh[(size_t)s * 64 + f]);
        a0 += fmaxf(xv.x + eav.x * w0a + eav.y * w1a + ba, 0.f);
        a1 += fmaxf(xv.y + eav.x * w0b + eav.y * w1b + bb, 0.f);
    }
    float2 xs = *(const float2*)&x[(size_t)wid * 64 + f];
    float2 r;
    r.x = xs.x + a0;
    r.y = xs.y + a1;
    *(float2*)&d_hpre[(size_t)wid * 64 + f] = r;
}

// D=128: warp per node, 4 feats/lane, edge-unroll 2. gather fp16 d_h1h; self fp32 d_h1.
__global__ void k_agg128(const float* __restrict__ We, const float* __restrict__ be, int n) {
    int wid = (blockIdx.x * blockDim.x + threadIdx.x) >> 5;
    if (wid >= n) return;
    int lane = threadIdx.x & 31;
    int f = lane * 4;
    float4 w0 = *(const float4*)&We[f];
    float4 w1 = *(const float4*)&We[128 + f];
    float4 bb = *(const float4*)&be[f];
    int beg = d_rowptr[wid], end = d_rowptr[wid + 1];
    float ax = 0.f, ay = 0.f, az = 0.f, aw = 0.f;
    int e = beg;
    for (; e + 2 <= end; e += 2) {
        int s0 = d_csrsrc[e], s1 = d_csrsrc[e + 1];
        float2 e0 = d_csrea[e], e1 = d_csrea[e + 1];
        float4 v0 = ld_h4(&d_h1h[(size_t)s0 * 128 + f]);
        float4 v1 = ld_h4(&d_h1h[(size_t)s1 * 128 + f]);
        ax += fmaxf(v0.x + e0.x * w0.x + e0.y * w1.x + bb.x, 0.f)
            + fmaxf(v1.x + e1.x * w0.x + e1.y * w1.x + bb.x, 0.f);
        ay += fmaxf(v0.y + e0.x * w0.y + e0.y * w1.y + bb.y, 0.f)
            + fmaxf(v1.y + e1.x * w0.y + e1.y * w1.y + bb.y, 0.f);
        az += fmaxf(v0.z + e0.x * w0.z + e0.y * w1.z + bb.z, 0.f)
            + fmaxf(v1.z + e1.x * w0.z + e1.y * w1.z + bb.z, 0.f);
        aw += fmaxf(v0.w + e0.x * w0.w + e0.y * w1.w + bb.w, 0.f)
            + fmaxf(v1.w + e1.x * w0.w + e1.y * w1.w + bb.w, 0.f);
    }
    for (; e < end; e++) {
        int s = d_csrsrc[e];
        float2 e0 = d_csrea[e];
        float4 v0 = ld_h4(&d_h1h[(size_t)s * 128 + f]);
        ax += fmaxf(v0.x + e0.x * w0.x + e0.y * w1.x + bb.x, 0.f);
        ay += fmaxf(v0.y + e0.x * w0.y + e0.y * w1.y + bb.y, 0.f);
        az += fmaxf(v0.z + e0.x * w0.z + e0.y * w1.z + bb.z, 0.f);
        aw += fmaxf(v0.w + e0.x * w0.w + e0.y * w1.w + bb.w, 0.f);
    }
    float4 xs = *(const float4*)&d_h1[(size_t)wid * 128 + f];
    float4 r;
    r.x = xs.x + ax; r.y = xs.y + ay; r.z = xs.z + az; r.w = xs.w + aw;
    *(float4*)&d_hpre[(size_t)wid * 128 + f] = r;
}

// ---------------- MLP + LayerNorm (fused, register tile of 16 nodes) ----------------
// GL=true : conv1 : out = LN(gelu(gelu(in@W1+b1)@W2+b2)) -> d_h1 (fp32) + d_h1h (fp16)
// GL=false: conv2 : out = LN(     gelu(in@W1+b1)@W2+b2 ) -> d_x0h (fp16)
template <int DIN, bool GL>
__global__ void k_mlp(const float* __restrict__ W1, const float* __restrict__ b1,
                      const float* __restrict__ W2, const float* __restrict__ b2,
                      const float* __restrict__ gm, const float* __restrict__ bt, int n) {
    __shared__ __align__(16) float in_sh[NB_MLP][DIN];
    __shared__ __align__(16) float t_sh[NB_MLP][128];
    __shared__ float u_sh[NB_MLP][129];   // padded: conflict-free LN reduce
    __shared__ float st[NB_MLP][2];

    int tid = threadIdx.x;
    int base = blockIdx.x * NB_MLP;
    for (int idx = tid; idx < NB_MLP * DIN; idx += 128) {
        int nn = idx / DIN, k = idx % DIN;
        int node = base + nn;
        in_sh[nn][k] = (node < n) ? __ldg(&d_hpre[(size_t)node * DIN + k]) : 0.f;
    }
    __syncthreads();
    int f = tid;
    float acc[NB_MLP];
    {
        float bv = __ldg(&b1[f]);
#pragma unroll
        for (int i = 0; i < NB_MLP; i++) acc[i] = bv;
    }
    for (int k = 0; k < DIN; k += 4) {
        float wa = __ldg(&W1[(k + 0) * 128 + f]);
        float wb = __ldg(&W1[(k + 1) * 128 + f]);
        float wc = __ldg(&W1[(k + 2) * 128 + f]);
        float wd = __ldg(&W1[(k + 3) * 128 + f]);
#pragma unroll
        for (int i = 0; i < NB_MLP; i++) {
            float4 iv = *(const float4*)&in_sh[i][k];
            acc[i] += iv.x * wa + iv.y * wb + iv.z * wc + iv.w * wd;
        }
    }
#pragma unroll
    for (int i = 0; i < NB_MLP; i++) t_sh[i][f] = gelu_f(acc[i]);
    __syncthreads();
    {
        float bv = __ldg(&b2[f]);
#pragma unroll
        for (int i = 0; i < NB_MLP; i++) acc[i] = bv;
    }
    for (int k = 0; k < 128; k += 4) {
        float wa = __ldg(&W2[(k + 0) * 128 + f]);
        float wb = __ldg(&W2[(k + 1) * 128 + f]);
        float wc = __ldg(&W2[(k + 2) * 128 + f]);
        float wd = __ldg(&W2[(k + 3) * 128 + f]);
#pragma unroll
        for (int i = 0; i < NB_MLP; i++) {
            float4 tv = *(const float4*)&t_sh[i][k];
            acc[i] += tv.x * wa + tv.y * wb + tv.z * wc + tv.w * wd;
        }
    }
#pragma unroll
    for (int i = 0; i < NB_MLP; i++) {
        float u = acc[i];
        if (GL) u = gelu_f(u);     // conv1 applies gelu BEFORE layernorm
        u_sh[i][f] = u;
    }
    __syncthreads();
    {
        int g = tid >> 3, l = tid & 7;   // group g (8 lanes) reduces node g
        float s = 0.f, q = 0.f;
#pragma unroll
        for (int m = 0; m < 16; m++) {
            float v = u_sh[g][l + 8 * m];
            s += v;
            q += v * v;
        }
#pragma unroll
        for (int off = 4; off > 0; off >>= 1) {
            s += __shfl_xor_sync(0xffffffffu, s, off);
            q += __shfl_xor_sync(0xffffffffu, q, off);
        }
        if (l == 0) {
            float mu = s * (1.f / 128.f);
            float var = q * (1.f / 128.f) - mu * mu;
            st[g][0] = mu;
            st[g][1] = rsqrtf(var + 1e-5f);
        }
    }
    __syncthreads();
    float gv = __ldg(&gm[f]), bv2 = __ldg(&bt[f]);
#pragma unroll
    for (int i = 0; i < NB_MLP; i++) {
        int node = base + i;
        if (node < n) {
            float v = (u_sh[i][f] - st[i][0]) * st[i][1] * gv + bv2;
            if (GL) {
                d_h1[(size_t)node * 128 + f] = v;
                d_h1h[(size_t)node * 128 + f] = __float2half(v);
            } else {
                d_x0h[(size_t)node * 128 + f] = __float2half(v);
            }
        }
    }
}

// ---------------- APPNP step (pull, warp per node, fp16 state, packed edges) -------
// insel: 0=d_x0h 1=d_pa 2=d_pb ; outsel: 1=d_pa 2=d_pb 3=fp32 extout
__global__ void k_appnp(int insel, int outsel, float* __restrict__ extout, int n) {
    const __half* __restrict__ hin = (insel == 0) ? d_x0h : ((insel == 1) ? d_pa : d_pb);
    __half* __restrict__ hout = (outsel == 1) ? d_pa : d_pb;
    int wid = (blockIdx.x * blockDim.x + threadIdx.x) >> 5;
    if (wid >= n) return;
    int lane = threadIdx.x & 31;
    int f = lane * 4;
    int beg = d_rowptr[wid], end = d_rowptr[wid + 1];
    float ax = 0.f, ay = 0.f, az = 0.f, aw = 0.f;
    int e = beg;
    for (; e + 4 <= end; e += 4) {
        int2 r0 = d_csredge[e],     r1 = d_csredge[e + 1];
        int2 r2 = d_csredge[e + 2], r3 = d_csredge[e + 3];
        float w0 = __int_as_float(r0.y), w1 = __int_as_float(r1.y);
        float w2 = __int_as_float(r2.y), w3 = __int_as_float(r3.y);
        float4 v0 = ld_h4(&hin[(size_t)r0.x * 128 + f]);
        float4 v1 = ld_h4(&hin[(size_t)r1.x * 128 + f]);
        float4 v2 = ld_h4(&hin[(size_t)r2.x * 128 + f]);
        float4 v3 = ld_h4(&hin[(size_t)r3.x * 128 + f]);
        ax += w0 * v0.x + w1 * v1.x + w2 * v2.x + w3 * v3.x;
        ay += w0 * v0.y + w1 * v1.y + w2 * v2.y + w3 * v3.y;
        az += w0 * v0.z + w1 * v1.z + w2 * v2.z + w3 * v3.z;
        aw += w0 * v0.w + w1 * v1.w + w2 * v2.w + w3 * v3.w;
    }
    for (; e < end; e++) {
        int2 re = d_csredge[e];
        float w = __int_as_float(re.y);
        float4 v = ld_h4(&hin[(size_t)re.x * 128 + f]);
        ax += w * v.x; ay += w * v.y; az += w * v.z; aw += w * v.w;
    }
    float sw = 1.f / ((float)d_deg[wid] + 1.f);
    float4 hv = ld_h4(&hin[(size_t)wid * 128 + f]);
    float4 xv = ld_h4(&d_x0h[(size_t)wid * 128 + f]);
    float rx = 0.9f * (ax + sw * hv.x) + 0.1f * xv.x;
    float ry = 0.9f * (ay + sw * hv.y) + 0.1f * xv.y;
    float rz = 0.9f * (az + sw * hv.z) + 0.1f * xv.z;
    float rw = 0.9f * (aw + sw * hv.w) + 0.1f * xv.w;
    if (outsel == 3) {
        float4 r; r.x = rx; r.y = ry; r.z = rz; r.w = rw;
        *(float4*)&extout[(size_t)wid * 128 + f] = r;
    } else {
        st_h4(&hout[(size_t)wid * 128 + f], rx, ry, rz, rw);
    }
}

// ---------------- gate + attentional pooling ----------------
__global__ void k_poolinit(float* __restrict__ outg) {
    int i = blockIdx.x * blockDim.x + threadIdx.x;
    if (i < 64) {
        d_bmax[i] = 0x007FFFFFu;   // ford(-inf)
        d_bsum[i] = 0.f;
    }
    if (i < 64 * 128) outg[i] = 0.f;
}
__global__ void k_gate(const float* __restrict__ h, const float* __restrict__ Wg1,
                       const float* __restrict__ bg1, const float* __restrict__ Wg2,
                       const float* __restrict__ bg2, const void* batch, int n) {
    __shared__ __align__(16) float hsh[4][128];
    __shared__ float wsum[8];
    int sub = threadIdx.x >> 6;        // 4 nodes / block, 64 threads each
    int j = threadIdx.x & 63;
    int node = blockIdx.x * 4 + sub;
    if (node < n) {
        hsh[sub][j]      = __ldg(&h[(size_t)node * 128 + j]);
        hsh[sub][j + 64] = __ldg(&h[(size_t)node * 128 + j + 64]);
    }
    __syncthreads();
    float c = 0.f;
    if (node < n) {
        float a = __ldg(&bg1[j]);
        for (int k = 0; k < 128; k += 4) {
            float4 hv = *(const float4*)&hsh[sub][k];
            a += hv.x * __ldg(&Wg1[(k + 0) * 64 + j]);
            a += hv.y * __ldg(&Wg1[(k + 1) * 64 + j]);
            a += hv.z * __ldg(&Wg1[(k + 2) * 64 + j]);
            a += hv.w * __ldg(&Wg1[(k + 3) * 64 + j]);
        }
        c = gelu_f(a) * __ldg(&Wg2[j]);
    }
#pragma unroll
    for (int off = 16; off > 0; off >>= 1) c += __shfl_xor_sync(0xffffffffu, c, off);
    if ((threadIdx.x & 31) == 0) wsum[threadIdx.x >> 5] = c;
    __syncthreads();
    if (node < n && j == 0) {
        float gvl = wsum[2 * sub] + wsum[2 * sub + 1] + __ldg(&bg2[0]);
        d_gate[node] = gvl;
        int b = ld_idx(batch, node);
        atomicMax(&d_bmax[b], ford(gvl));
    }
}
__global__ void k_exp(const void* batch, int n) {
    int i = blockIdx.x * blockDim.x + threadIdx.x;
    if (i >= n) return;
    int b = ld_idx(batch, i);
    float ev = expf(d_gate[i] - funord(d_bmax[b]));
    d_expg[i] = ev;
    atomicAdd(&d_bsum[b], ev);
}
__global__ void k_pool(const float* __restrict__ h, const void* batch,
                       float* __restrict__ outg, int n) {
    int base = blockIdx.x * 64;           // 64 sorted nodes per block, pre-aggregate per batch
    int f = threadIdx.x;                  // 128 threads = feature
    float acc = 0.f;
    int cb = -1;
    int lim = n - base;
    if (lim > 64) lim = 64;
    for (int j = 0; j < lim; j++) {
        int i = base + j;
        int b = ld_idx(batch, i);
        if (b != cb) {
            if (cb >= 0) atomicAdd(&outg[cb * 128 + f], acc);
            acc = 0.f;
            cb = b;
        }
        float a = d_expg[i] / d_bsum[b];
        acc += a * __ldg(&h[(size_t)i * 128 + f]);
    }
    if (cb >= 0) atomicAdd(&outg[cb * 128 + f], acc);
}

// ---------------- launch ----------------
extern "C" void kernel_launch(void* const* d_in, const int* in_sizes, int n_in,
                              void* d_out, int out_size) {
    const float* x   = (const float*)d_in[0];
    const void*  ei  = d_in[1];
    const void*  bat = d_in[2];
    const float* ea  = (const float*)d_in[3];
    const float* We1 = (const float*)d_in[4];
    const float* be1 = (const float*)d_in[5];
    const float* W1a = (const float*)d_in[6];
    const float* b1a = (const float*)d_in[7];
    const float* W1b = (const float*)d_in[8];
    const float* b1b = (const float*)d_in[9];
    const float* g1  = (const float*)d_in[10];
    const float* bn1 = (const float*)d_in[11];
    const float* We2 = (const float*)d_in[12];
    const float* be2 = (const float*)d_in[13];
    const float* W2a = (const float*)d_in[14];
    const float* b2a = (const float*)d_in[15];
    const float* W2b = (const float*)d_in[16];
    const float* b2b = (const float*)d_in[17];
    const float* g2  = (const float*)d_in[18];
    const float* bn2 = (const float*)d_in[19];
    const float* Wg1 = (const float*)d_in[20];
    const float* bg1 = (const float*)d_in[21];
    const float* Wg2 = (const float*)d_in[22];
    const float* bg2 = (const float*)d_in[23];

    int n = in_sizes[0] / 64;    // 100000
    int e = in_sizes[3] / 2;     // 1600000
    float* out = (float*)d_out;
    float* outh = out;                        // h: [N,128]
    float* outg = out + (size_t)n * 128;      // g: [B,128]

    // CSR preprocessing
    k_detect<<<1, 32>>>(ei, (long long)2 * e);
    k_prep<<<(n * 64 + 255) / 256, 256>>>(x, n, n * 64);
    k_count<<<(e + 255) / 256, 256>>>(ei, e);
    int sb = (n + 1023) / 1024;
    k_scan1<<<sb, 1024>>>(n);
    k_scan2<<<1, 128>>>(sb);
    k_scan3<<<(n + 255) / 256, 256>>>(n, e);
    k_build<<<(e + 255) / 256, 256>>>(ei, ea, e);

    int wb = (n + 7) / 8;                     // warp-per-node kernels: 8 warps / 256-thread block
    int mb = (n + NB_MLP - 1) / NB_MLP;

    // conv1 + conv2
    k_agg64<<<wb, 256>>>(x, We1, be1, n);
    k_mlp<64, true><<<mb, 128>>>(W1a, b1a, W1b, b1b, g1, bn1, n);
    k_agg128<<<wb, 256>>>(We2, be2, n);
    k_mlp<128, false><<<mb, 128>>>(W2a, b2a, W2b, b2b, g2, bn2, n);

    // APPNP: 16 steps, fp16 ping-pong; final step accumulates fp32 and writes d_out h
    for (int s = 0; s < 16; s++) {
        int insel  = (s == 0) ? 0 : ((s & 1) ? 1 : 2);
        int outsel = (s == 15) ? 3 : ((s & 1) ? 2 : 1);
        k_appnp<<<wb, 256>>>(insel, outsel, outh, n);
    }

    // gate + per-graph softmax pooling
    k_poolinit<<<32, 256>>>(outg);
    k_gate<<<(n + 3) / 4, 256>>>(outh, Wg1, bg1, Wg2, bg2, bat, n);
    k_exp<<<(n + 255) / 256, 256>>>(bat, n);
    k_pool<<<(n + 63) / 64, 128>>>(outh, bat, outg, n);
}